// round 1
// baseline (speedup 1.0000x reference)
#include <cuda_runtime.h>
#include <cuda_bf16.h>
#include <math_constants.h>

// Problem constants
#define BB 2
#define NN 2048
#define HH 8
#define DD 64
#define FIN 512
#define HD 512            // H*D
#define EPS 1e-5f
#define SCALE 0.125f      // D^-0.5 = 1/8
#define INV_H 0.125f      // 1/H

// Scratch (device globals — allowed; no runtime allocation)
__device__ float g_h[BB * NN * HD];                 // projected features [b][n][h*64+d]  (8 MB)
__device__ float g_S[(size_t)BB * HH * NN * NN];    // scores -> probs   [b][h][n][m]     (268 MB)
__device__ float g_O[BB * NN * HD];                 // attention output  [b][n][h*64+d]   (8 MB)

// ---------------------------------------------------------------------------
// K1: h = x @ W + b          A[4096,512] * W[512,512] -> C[4096,512]
// 64x64 tile, BK=16, 256 threads, 4x4 per thread
// ---------------------------------------------------------------------------
__global__ void k_proj(const float* __restrict__ x, const float* __restrict__ W,
                       const float* __restrict__ bias) {
    __shared__ float As[64][17];
    __shared__ float Bs[16][65];

    const int tx = threadIdx.x;       // 0..15
    const int ty = threadIdx.y;       // 0..15
    const int t  = ty * 16 + tx;      // 0..255
    const int row0 = blockIdx.y * 64;
    const int col0 = blockIdx.x * 64;

    float acc[4][4];
    #pragma unroll
    for (int i = 0; i < 4; i++)
        #pragma unroll
        for (int j = 0; j < 4; j++) acc[i][j] = 0.f;

    for (int k0 = 0; k0 < FIN; k0 += 16) {
        // load A tile 64x16 (1024 elems, 4 per thread)
        #pragma unroll
        for (int i = 0; i < 4; i++) {
            int idx = t + i * 256;
            int r = idx >> 4, c = idx & 15;
            As[r][c] = x[(size_t)(row0 + r) * FIN + k0 + c];
        }
        // load B tile 16x64
        #pragma unroll
        for (int i = 0; i < 4; i++) {
            int idx = t + i * 256;
            int r = idx >> 6, c = idx & 63;
            Bs[r][c] = W[(size_t)(k0 + r) * HD + col0 + c];
        }
        __syncthreads();
        #pragma unroll
        for (int kk = 0; kk < 16; kk++) {
            float a[4], bv[4];
            #pragma unroll
            for (int i = 0; i < 4; i++) a[i] = As[ty * 4 + i][kk];
            #pragma unroll
            for (int j = 0; j < 4; j++) bv[j] = Bs[kk][tx * 4 + j];
            #pragma unroll
            for (int i = 0; i < 4; i++)
                #pragma unroll
                for (int j = 0; j < 4; j++) acc[i][j] += a[i] * bv[j];
        }
        __syncthreads();
    }

    #pragma unroll
    for (int i = 0; i < 4; i++) {
        int r = row0 + ty * 4 + i;
        #pragma unroll
        for (int j = 0; j < 4; j++) {
            int c = col0 + tx * 4 + j;
            g_h[(size_t)r * HD + c] = acc[i][j] + bias[c];
        }
    }
}

// ---------------------------------------------------------------------------
// K2: S[b,h,n,m] = SCALE * sum_d h[b,n,h*64+d] * h[b,m,h*64+d]   (NT GEMM)
// grid (N/64, N/64, B*H), 64x64 tile, full K=64
// ---------------------------------------------------------------------------
__global__ void k_scores() {
    __shared__ float Qs[64][65];
    __shared__ float Kt[64][65];   // transposed: Kt[d][m]

    const int tx = threadIdx.x, ty = threadIdx.y;
    const int t = ty * 16 + tx;
    const int col0 = blockIdx.x * 64;   // m
    const int row0 = blockIdx.y * 64;   // n
    const int bh   = blockIdx.z;        // b*8+h
    const int b = bh >> 3, hh = bh & 7;

    const float* Hbase = g_h + (size_t)b * NN * HD + hh * DD;

    // load Q tile [64 rows][64 d]  (16 elems per thread)
    #pragma unroll
    for (int i = 0; i < 16; i++) {
        int idx = t + i * 256;
        int r = idx >> 6, c = idx & 63;
        Qs[r][c] = Hbase[(size_t)(row0 + r) * HD + c];
    }
    // load K tile transposed: Kt[d][m-local]
    #pragma unroll
    for (int i = 0; i < 16; i++) {
        int idx = t + i * 256;
        int r = idx >> 6, c = idx & 63;        // r = m-local, c = d
        Kt[c][r] = Hbase[(size_t)(col0 + r) * HD + c];
    }
    __syncthreads();

    float acc[4][4];
    #pragma unroll
    for (int i = 0; i < 4; i++)
        #pragma unroll
        for (int j = 0; j < 4; j++) acc[i][j] = 0.f;

    #pragma unroll
    for (int kk = 0; kk < 64; kk++) {
        float a[4], bv[4];
        #pragma unroll
        for (int i = 0; i < 4; i++) a[i] = Qs[ty * 4 + i][kk];
        #pragma unroll
        for (int j = 0; j < 4; j++) bv[j] = Kt[kk][tx * 4 + j];
        #pragma unroll
        for (int i = 0; i < 4; i++)
            #pragma unroll
            for (int j = 0; j < 4; j++) acc[i][j] += a[i] * bv[j];
    }

    float* Sb = g_S + (size_t)bh * NN * NN;
    #pragma unroll
    for (int i = 0; i < 4; i++) {
        int r = row0 + ty * 4 + i;
        #pragma unroll
        for (int j = 0; j < 4; j++) {
            int c = col0 + tx * 4 + j;
            Sb[(size_t)r * NN + c] = acc[i][j] * SCALE;
        }
    }
}

// ---------------------------------------------------------------------------
// K3: masked softmax per row + head-mean accumulation
// grid (N, B), 256 threads. Writes probs back to g_S and mean to d_out tail.
// ---------------------------------------------------------------------------
__global__ void k_softmax(const int* __restrict__ adj, float* __restrict__ out_mean) {
    __shared__ unsigned char mask[NN];
    __shared__ float srow[NN];
    __shared__ float meanrow[NN];
    __shared__ float red[256];

    const int n = blockIdx.x;
    const int b = blockIdx.y;
    const int t = threadIdx.x;

    const int* arow = adj + (size_t)b * NN * NN + (size_t)n * NN;
    for (int m = t; m < NN; m += 256) {
        mask[m] = (arow[m] != 0);
        meanrow[m] = 0.f;
    }
    __syncthreads();

    for (int hh = 0; hh < HH; hh++) {
        float* Srow = g_S + ((size_t)(b * HH + hh) * NN + n) * NN;

        // load + mask, local max
        float lmax = -CUDART_INF_F;
        for (int m = t; m < NN; m += 256) {
            float v = mask[m] ? Srow[m] : -CUDART_INF_F;
            srow[m] = v;
            lmax = fmaxf(lmax, v);
        }
        // block reduce max
        red[t] = lmax;
        __syncthreads();
        for (int s = 128; s > 0; s >>= 1) {
            if (t < s) red[t] = fmaxf(red[t], red[t + s]);
            __syncthreads();
        }
        float rmax = red[0];
        __syncthreads();

        // sum of exp
        float lsum = 0.f;
        for (int m = t; m < NN; m += 256) {
            float e = __expf(srow[m] - rmax);   // exp(-inf)=0
            srow[m] = e;
            lsum += e;
        }
        red[t] = lsum;
        __syncthreads();
        for (int s = 128; s > 0; s >>= 1) {
            if (t < s) red[t] += red[t + s];
            __syncthreads();
        }
        float inv = 1.f / red[0];
        __syncthreads();

        for (int m = t; m < NN; m += 256) {
            float p = srow[m] * inv;
            Srow[m] = p;
            meanrow[m] += p * INV_H;
        }
        __syncthreads();
    }

    float* mrow = out_mean + ((size_t)b * NN + n) * NN;
    for (int m = t; m < NN; m += 256) mrow[m] = meanrow[m];
}

// ---------------------------------------------------------------------------
// K4: O[b,n,h*64+d] = sum_m P[b,h,n,m] * h[b,m,h*64+d]   (NN GEMM, Nt=D=64)
// grid (N/64, B*H), 64x64 tile, BK=64
// ---------------------------------------------------------------------------
__global__ void k_av() {
    __shared__ float Ps[64][65];
    __shared__ float Vs[64][65];

    const int tx = threadIdx.x, ty = threadIdx.y;
    const int t = ty * 16 + tx;
    const int row0 = blockIdx.x * 64;
    const int bh   = blockIdx.y;
    const int b = bh >> 3, hh = bh & 7;

    const float* Pb = g_S + (size_t)bh * NN * NN;
    const float* Vb = g_h + (size_t)b * NN * HD + hh * DD;

    float acc[4][4];
    #pragma unroll
    for (int i = 0; i < 4; i++)
        #pragma unroll
        for (int j = 0; j < 4; j++) acc[i][j] = 0.f;

    for (int k0 = 0; k0 < NN; k0 += 64) {
        #pragma unroll
        for (int i = 0; i < 16; i++) {
            int idx = t + i * 256;
            int r = idx >> 6, c = idx & 63;
            Ps[r][c] = Pb[(size_t)(row0 + r) * NN + k0 + c];
        }
        #pragma unroll
        for (int i = 0; i < 16; i++) {
            int idx = t + i * 256;
            int r = idx >> 6, c = idx & 63;   // r = m-local, c = d
            Vs[r][c] = Vb[(size_t)(k0 + r) * HD + c];
        }
        __syncthreads();
        #pragma unroll
        for (int kk = 0; kk < 64; kk++) {
            float a[4], bv[4];
            #pragma unroll
            for (int i = 0; i < 4; i++) a[i] = Ps[ty * 4 + i][kk];
            #pragma unroll
            for (int j = 0; j < 4; j++) bv[j] = Vs[kk][tx * 4 + j];
            #pragma unroll
            for (int i = 0; i < 4; i++)
                #pragma unroll
                for (int j = 0; j < 4; j++) acc[i][j] += a[i] * bv[j];
        }
        __syncthreads();
    }

    #pragma unroll
    for (int i = 0; i < 4; i++) {
        int r = row0 + ty * 4 + i;
        #pragma unroll
        for (int j = 0; j < 4; j++) {
            int c = tx * 4 + j;   // d in 0..63
            g_O[((size_t)b * NN + r) * HD + hh * DD + c] = acc[i][j];
        }
    }
}

// ---------------------------------------------------------------------------
// K5: LayerNorm over model dim (512), write to d_out head
// grid (B*N), 128 threads
// ---------------------------------------------------------------------------
__global__ void k_ln(const float* __restrict__ gamma, const float* __restrict__ beta,
                     float* __restrict__ out) {
    __shared__ float red[128];
    __shared__ float red2[128];

    const int row = blockIdx.x;            // b*N+n
    const int t = threadIdx.x;
    const float* v = g_O + (size_t)row * HD;

    float s = 0.f, s2 = 0.f;
    float vals[4];
    #pragma unroll
    for (int i = 0; i < 4; i++) {
        vals[i] = v[t + i * 128];
        s += vals[i];
        s2 += vals[i] * vals[i];
    }
    red[t] = s; red2[t] = s2;
    __syncthreads();
    for (int st = 64; st > 0; st >>= 1) {
        if (t < st) { red[t] += red[t + st]; red2[t] += red2[t + st]; }
        __syncthreads();
    }
    const float mu = red[0] * (1.f / HD);
    const float var = red2[0] * (1.f / HD) - mu * mu;
    const float rstd = rsqrtf(var + EPS);

    float* orow = out + (size_t)row * HD;
    #pragma unroll
    for (int i = 0; i < 4; i++) {
        int c = t + i * 128;
        orow[c] = (vals[i] - mu) * rstd * gamma[c] + beta[c];
    }
}

// ---------------------------------------------------------------------------
extern "C" void kernel_launch(void* const* d_in, const int* in_sizes, int n_in,
                              void* d_out, int out_size) {
    const float* x     = (const float*)d_in[0];   // [B,N,FIN]
    const int*   adj   = (const int*)d_in[1];     // [B,N,N]
    const float* W_w   = (const float*)d_in[2];   // [FIN,HD]
    const float* W_b   = (const float*)d_in[3];   // [HD]
    const float* gamma = (const float*)d_in[4];   // [HD]
    const float* beta  = (const float*)d_in[5];   // [HD]
    float* out = (float*)d_out;

    float* out_mean = out + (size_t)BB * NN * HD;   // second output: attn.mean over heads

    dim3 blk16(16, 16);

    // K1: projection GEMM
    k_proj<<<dim3(HD / 64, (BB * NN) / 64), blk16>>>(x, W_w, W_b);

    // K2: scores
    k_scores<<<dim3(NN / 64, NN / 64, BB * HH), blk16>>>();

    // K3: masked softmax + head mean
    k_softmax<<<dim3(NN, BB), 256>>>(adj, out_mean);

    // K4: attention * V
    k_av<<<dim3(NN / 64, BB * HH), blk16>>>();

    // K5: LayerNorm -> out
    k_ln<<<BB * NN, 128>>>(gamma, beta, out);
}

// round 2
// speedup vs baseline: 1.8514x; 1.8514x over previous
#include <cuda_runtime.h>
#include <cuda_bf16.h>
#include <math_constants.h>
#include <mma.h>

using namespace nvcuda;

// Problem constants
#define BB 2
#define NN 2048
#define HH 8
#define DD 64
#define FIN 512
#define HD 512            // H*D
#define EPS 1e-5f
#define SCALE 0.125f      // D^-0.5
#define INV_H 0.125f      // 1/H

// Scratch (device globals — allowed; no runtime allocation)
__device__ float g_h[BB * NN * HD];                 // projected features [b][n][h*64+d]
__device__ float g_S[(size_t)BB * HH * NN * NN];    // scores -> probs   [b][h][n][m]
__device__ float g_O[BB * NN * HD];                 // attention output  [b][n][h*64+d]

__device__ __forceinline__ float f2tf32(float x) {
    float r;
    asm("cvt.rna.tf32.f32 %0, %1;" : "=f"(r) : "f"(x));
    return r;
}

// ---------------------------------------------------------------------------
// K1: h = x @ W + b   (tf32 wmma)  A[4096,512] * W[512,512] -> g_h
// CTA 64x64 tile, 128 threads (4 warps, each 32x32), K chunks of 64
// ---------------------------------------------------------------------------
__global__ void k_proj(const float* __restrict__ x, const float* __restrict__ W,
                       const float* __restrict__ bias) {
    __shared__ float Xs[64][72];
    __shared__ float Ws[64][72];

    const int t = threadIdx.x;               // 0..127
    const int wid = t >> 5;
    const int warp_m = (wid & 1) * 32;
    const int warp_n = (wid >> 1) * 32;
    const int row0 = blockIdx.y * 64;
    const int col0 = blockIdx.x * 64;

    wmma::fragment<wmma::accumulator, 16, 16, 8, float> c[2][2];
    #pragma unroll
    for (int i = 0; i < 2; i++)
        #pragma unroll
        for (int j = 0; j < 2; j++) wmma::fill_fragment(c[i][j], 0.f);

    for (int k0 = 0; k0 < FIN; k0 += 64) {
        // load 64x64 X and 64x64 W tiles (8 float4 per thread per tile)
        #pragma unroll
        for (int i = 0; i < 8; i++) {
            int idx = t + i * 128;
            int r = idx >> 4, c4 = idx & 15;
            float4 v = *(const float4*)&x[(size_t)(row0 + r) * FIN + k0 + c4 * 4];
            v.x = f2tf32(v.x); v.y = f2tf32(v.y); v.z = f2tf32(v.z); v.w = f2tf32(v.w);
            *(float4*)&Xs[r][c4 * 4] = v;
            float4 w = *(const float4*)&W[(size_t)(k0 + r) * HD + col0 + c4 * 4];
            w.x = f2tf32(w.x); w.y = f2tf32(w.y); w.z = f2tf32(w.z); w.w = f2tf32(w.w);
            *(float4*)&Ws[r][c4 * 4] = w;
        }
        __syncthreads();

        #pragma unroll
        for (int kk = 0; kk < 8; kk++) {
            wmma::fragment<wmma::matrix_a, 16, 16, 8, wmma::precision::tf32, wmma::row_major> a[2];
            wmma::fragment<wmma::matrix_b, 16, 16, 8, wmma::precision::tf32, wmma::row_major> bfr[2];
            #pragma unroll
            for (int i = 0; i < 2; i++)
                wmma::load_matrix_sync(a[i], &Xs[warp_m + 16 * i][kk * 8], 72);
            #pragma unroll
            for (int j = 0; j < 2; j++)
                wmma::load_matrix_sync(bfr[j], &Ws[kk * 8][warp_n + 16 * j], 72);
            #pragma unroll
            for (int i = 0; i < 2; i++)
                #pragma unroll
                for (int j = 0; j < 2; j++)
                    wmma::mma_sync(c[i][j], a[i], bfr[j], c[i][j]);
        }
        __syncthreads();
    }

    // stage result in smem (reuse Xs+Ws region), add bias, write out
    __shared__ float Stage[64][72];
    #pragma unroll
    for (int i = 0; i < 2; i++)
        #pragma unroll
        for (int j = 0; j < 2; j++)
            wmma::store_matrix_sync(&Stage[warp_m + 16 * i][warp_n + 16 * j], c[i][j], 72,
                                    wmma::mem_row_major);
    __syncthreads();
    #pragma unroll
    for (int i = 0; i < 8; i++) {
        int idx = t + i * 128;
        int r = idx >> 4, c4 = idx & 15;
        float4 v = *(float4*)&Stage[r][c4 * 4];
        float4 bb = *(const float4*)&bias[col0 + c4 * 4];
        v.x += bb.x; v.y += bb.y; v.z += bb.z; v.w += bb.w;
        *(float4*)&g_h[(size_t)(row0 + r) * HD + col0 + c4 * 4] = v;
    }
}

// ---------------------------------------------------------------------------
// K2: S = SCALE * Q Kᵀ  (tf32 wmma)  per (b,h): [2048,64]x[64,2048]
// CTA 64x64 tile, 4 warps, full K=64 in smem
// ---------------------------------------------------------------------------
__global__ void k_scores() {
    __shared__ float Qs[64][72];
    __shared__ float Ks[64][72];   // row m, col d — used as col_major B (d x m)

    const int t = threadIdx.x;
    const int wid = t >> 5;
    const int warp_m = (wid & 1) * 32;
    const int warp_n = (wid >> 1) * 32;
    const int col0 = blockIdx.x * 64;   // m
    const int row0 = blockIdx.y * 64;   // n
    const int bh = blockIdx.z;
    const int b = bh >> 3, hh = bh & 7;

    const float* Hbase = g_h + (size_t)b * NN * HD + hh * DD;

    #pragma unroll
    for (int i = 0; i < 8; i++) {
        int idx = t + i * 128;
        int r = idx >> 4, c4 = idx & 15;
        float4 q = *(const float4*)&Hbase[(size_t)(row0 + r) * HD + c4 * 4];
        q.x = f2tf32(q.x); q.y = f2tf32(q.y); q.z = f2tf32(q.z); q.w = f2tf32(q.w);
        *(float4*)&Qs[r][c4 * 4] = q;
        float4 k = *(const float4*)&Hbase[(size_t)(col0 + r) * HD + c4 * 4];
        k.x = f2tf32(k.x); k.y = f2tf32(k.y); k.z = f2tf32(k.z); k.w = f2tf32(k.w);
        *(float4*)&Ks[r][c4 * 4] = k;
    }
    __syncthreads();

    wmma::fragment<wmma::accumulator, 16, 16, 8, float> c[2][2];
    #pragma unroll
    for (int i = 0; i < 2; i++)
        #pragma unroll
        for (int j = 0; j < 2; j++) wmma::fill_fragment(c[i][j], 0.f);

    #pragma unroll
    for (int kk = 0; kk < 8; kk++) {
        wmma::fragment<wmma::matrix_a, 16, 16, 8, wmma::precision::tf32, wmma::row_major> a[2];
        wmma::fragment<wmma::matrix_b, 16, 16, 8, wmma::precision::tf32, wmma::col_major> bfr[2];
        #pragma unroll
        for (int i = 0; i < 2; i++)
            wmma::load_matrix_sync(a[i], &Qs[warp_m + 16 * i][kk * 8], 72);
        #pragma unroll
        for (int j = 0; j < 2; j++)
            wmma::load_matrix_sync(bfr[j], &Ks[warp_n + 16 * j][kk * 8], 72);
        #pragma unroll
        for (int i = 0; i < 2; i++)
            #pragma unroll
            for (int j = 0; j < 2; j++)
                wmma::mma_sync(c[i][j], a[i], bfr[j], c[i][j]);
    }

    float* Sb = g_S + (size_t)bh * NN * NN;
    #pragma unroll
    for (int i = 0; i < 2; i++)
        #pragma unroll
        for (int j = 0; j < 2; j++) {
            #pragma unroll
            for (int e = 0; e < c[i][j].num_elements; e++) c[i][j].x[e] *= SCALE;
            wmma::store_matrix_sync(
                Sb + (size_t)(row0 + warp_m + 16 * i) * NN + col0 + warp_n + 16 * j,
                c[i][j], NN, wmma::mem_row_major);
        }
}

// ---------------------------------------------------------------------------
// K3: masked softmax per row + head-mean  (unchanged structure)
// ---------------------------------------------------------------------------
__global__ void k_softmax(const int* __restrict__ adj, float* __restrict__ out_mean) {
    __shared__ unsigned char mask[NN];
    __shared__ float srow[NN];
    __shared__ float meanrow[NN];
    __shared__ float red[256];

    const int n = blockIdx.x;
    const int b = blockIdx.y;
    const int t = threadIdx.x;

    const int* arow = adj + (size_t)b * NN * NN + (size_t)n * NN;
    for (int m = t; m < NN; m += 256) {
        mask[m] = (arow[m] != 0);
        meanrow[m] = 0.f;
    }
    __syncthreads();

    for (int hh = 0; hh < HH; hh++) {
        float* Srow = g_S + ((size_t)(b * HH + hh) * NN + n) * NN;

        float lmax = -CUDART_INF_F;
        for (int m = t; m < NN; m += 256) {
            float v = mask[m] ? Srow[m] : -CUDART_INF_F;
            srow[m] = v;
            lmax = fmaxf(lmax, v);
        }
        red[t] = lmax;
        __syncthreads();
        for (int s = 128; s > 0; s >>= 1) {
            if (t < s) red[t] = fmaxf(red[t], red[t + s]);
            __syncthreads();
        }
        float rmax = red[0];
        __syncthreads();

        float lsum = 0.f;
        for (int m = t; m < NN; m += 256) {
            float e = __expf(srow[m] - rmax);
            srow[m] = e;
            lsum += e;
        }
        red[t] = lsum;
        __syncthreads();
        for (int s = 128; s > 0; s >>= 1) {
            if (t < s) red[t] += red[t + s];
            __syncthreads();
        }
        float inv = 1.f / red[0];
        __syncthreads();

        for (int m = t; m < NN; m += 256) {
            float p = srow[m] * inv;
            Srow[m] = p;
            meanrow[m] += p * INV_H;
        }
        __syncthreads();
    }

    float* mrow = out_mean + ((size_t)b * NN + n) * NN;
    for (int m = t; m < NN; m += 256) mrow[m] = meanrow[m];
}

// ---------------------------------------------------------------------------
// K4: O = P V  (tf32 wmma)  per (b,h): [2048,2048]x[2048,64]
// CTA 64 rows x 64 cols(D), 4 warps, K chunks of 64
// ---------------------------------------------------------------------------
__global__ void k_av() {
    __shared__ float Ps[64][72];
    __shared__ float Vs[64][72];

    const int t = threadIdx.x;
    const int wid = t >> 5;
    const int warp_m = (wid & 1) * 32;
    const int warp_n = (wid >> 1) * 32;
    const int row0 = blockIdx.x * 64;
    const int bh = blockIdx.y;
    const int b = bh >> 3, hh = bh & 7;

    const float* Pb = g_S + (size_t)bh * NN * NN;
    const float* Vb = g_h + (size_t)b * NN * HD + hh * DD;

    wmma::fragment<wmma::accumulator, 16, 16, 8, float> c[2][2];
    #pragma unroll
    for (int i = 0; i < 2; i++)
        #pragma unroll
        for (int j = 0; j < 2; j++) wmma::fill_fragment(c[i][j], 0.f);

    for (int k0 = 0; k0 < NN; k0 += 64) {
        #pragma unroll
        for (int i = 0; i < 8; i++) {
            int idx = t + i * 128;
            int r = idx >> 4, c4 = idx & 15;
            float4 p = *(const float4*)&Pb[(size_t)(row0 + r) * NN + k0 + c4 * 4];
            p.x = f2tf32(p.x); p.y = f2tf32(p.y); p.z = f2tf32(p.z); p.w = f2tf32(p.w);
            *(float4*)&Ps[r][c4 * 4] = p;
            float4 v = *(const float4*)&Vb[(size_t)(k0 + r) * HD + c4 * 4];
            v.x = f2tf32(v.x); v.y = f2tf32(v.y); v.z = f2tf32(v.z); v.w = f2tf32(v.w);
            *(float4*)&Vs[r][c4 * 4] = v;
        }
        __syncthreads();

        #pragma unroll
        for (int kk = 0; kk < 8; kk++) {
            wmma::fragment<wmma::matrix_a, 16, 16, 8, wmma::precision::tf32, wmma::row_major> a[2];
            wmma::fragment<wmma::matrix_b, 16, 16, 8, wmma::precision::tf32, wmma::row_major> bfr[2];
            #pragma unroll
            for (int i = 0; i < 2; i++)
                wmma::load_matrix_sync(a[i], &Ps[warp_m + 16 * i][kk * 8], 72);
            #pragma unroll
            for (int j = 0; j < 2; j++)
                wmma::load_matrix_sync(bfr[j], &Vs[kk * 8][warp_n + 16 * j], 72);
            #pragma unroll
            for (int i = 0; i < 2; i++)
                #pragma unroll
                for (int j = 0; j < 2; j++)
                    wmma::mma_sync(c[i][j], a[i], bfr[j], c[i][j]);
        }
        __syncthreads();
    }

    #pragma unroll
    for (int i = 0; i < 2; i++)
        #pragma unroll
        for (int j = 0; j < 2; j++)
            wmma::store_matrix_sync(
                g_O + ((size_t)b * NN + row0 + warp_m + 16 * i) * HD + hh * DD + warp_n + 16 * j,
                c[i][j], HD, wmma::mem_row_major);
}

// ---------------------------------------------------------------------------
// K5: LayerNorm over model dim (512) -> d_out head
// ---------------------------------------------------------------------------
__global__ void k_ln(const float* __restrict__ gamma, const float* __restrict__ beta,
                     float* __restrict__ out) {
    __shared__ float red[128];
    __shared__ float red2[128];

    const int row = blockIdx.x;
    const int t = threadIdx.x;
    const float* v = g_O + (size_t)row * HD;

    float s = 0.f, s2 = 0.f;
    float vals[4];
    #pragma unroll
    for (int i = 0; i < 4; i++) {
        vals[i] = v[t + i * 128];
        s += vals[i];
        s2 += vals[i] * vals[i];
    }
    red[t] = s; red2[t] = s2;
    __syncthreads();
    for (int st = 64; st > 0; st >>= 1) {
        if (t < st) { red[t] += red[t + st]; red2[t] += red2[t + st]; }
        __syncthreads();
    }
    const float mu = red[0] * (1.f / HD);
    const float var = red2[0] * (1.f / HD) - mu * mu;
    const float rstd = rsqrtf(var + EPS);

    float* orow = out + (size_t)row * HD;
    #pragma unroll
    for (int i = 0; i < 4; i++) {
        int c = t + i * 128;
        orow[c] = (vals[i] - mu) * rstd * gamma[c] + beta[c];
    }
}

// ---------------------------------------------------------------------------
extern "C" void kernel_launch(void* const* d_in, const int* in_sizes, int n_in,
                              void* d_out, int out_size) {
    const float* x     = (const float*)d_in[0];
    const int*   adj   = (const int*)d_in[1];
    const float* W_w   = (const float*)d_in[2];
    const float* W_b   = (const float*)d_in[3];
    const float* gamma = (const float*)d_in[4];
    const float* beta  = (const float*)d_in[5];
    float* out = (float*)d_out;
    float* out_mean = out + (size_t)BB * NN * HD;

    k_proj<<<dim3(HD / 64, (BB * NN) / 64), 128>>>(x, W_w, W_b);
    k_scores<<<dim3(NN / 64, NN / 64, BB * HH), 128>>>();
    k_softmax<<<dim3(NN, BB), 256>>>(adj, out_mean);
    k_av<<<dim3(NN / 64, BB * HH), 128>>>();
    k_ln<<<BB * NN, 128>>>(gamma, beta, out);
}

// round 3
// speedup vs baseline: 1.9436x; 1.0498x over previous
#include <cuda_runtime.h>
#include <cuda_bf16.h>
#include <math_constants.h>
#include <mma.h>

using namespace nvcuda;

#define BB 2
#define NN 2048
#define HH 8
#define DD 64
#define FIN 512
#define HD 512
#define EPS 1e-5f
#define SCALE 0.125f
#define NW (NN / 32)      // 64 mask words per row

// Device scratch
__device__ float g_h[BB * NN * HD];                    // projected features
__device__ float g_S[(size_t)BB * HH * NN * NN];       // unnormalized exp(e) values
__device__ float g_O[BB * NN * HD];                    // attention output (normalized)
__device__ float g_rowsum[BB * HH * NN];               // per-row exp sums
__device__ unsigned g_mask[(size_t)BB * NN * NW];      // adjacency bitmask

__device__ __forceinline__ float f2tf32(float x) {
    float r;
    asm("cvt.rna.tf32.f32 %0, %1;" : "=f"(r) : "f"(x));
    return r;
}

// ---------------------------------------------------------------------------
// K0: pack adj -> bitmask
// ---------------------------------------------------------------------------
__global__ void k_pack(const int* __restrict__ adj) {
    const int row = blockIdx.x;          // b*N + n
    const int t = threadIdx.x;           // 256
    const int warp = t >> 5, lane = t & 31;
    const int* arow = adj + (size_t)row * NN;
    #pragma unroll
    for (int j = warp; j < NW; j += 8) {
        unsigned bit = (arow[j * 32 + lane] != 0) ? 1u : 0u;
        unsigned word = __ballot_sync(0xffffffffu, bit);
        if (lane == 0) g_mask[(size_t)row * NW + j] = word;
    }
}

// ---------------------------------------------------------------------------
// K1: h = x @ W + b   (tf32 wmma)
// ---------------------------------------------------------------------------
__global__ void k_proj(const float* __restrict__ x, const float* __restrict__ W,
                       const float* __restrict__ bias) {
    __shared__ float Xs[64][72];
    __shared__ float Ws[64][72];

    const int t = threadIdx.x;
    const int wid = t >> 5;
    const int warp_m = (wid & 1) * 32;
    const int warp_n = (wid >> 1) * 32;
    const int row0 = blockIdx.y * 64;
    const int col0 = blockIdx.x * 64;

    wmma::fragment<wmma::accumulator, 16, 16, 8, float> c[2][2];
    #pragma unroll
    for (int i = 0; i < 2; i++)
        #pragma unroll
        for (int j = 0; j < 2; j++) wmma::fill_fragment(c[i][j], 0.f);

    for (int k0 = 0; k0 < FIN; k0 += 64) {
        #pragma unroll
        for (int i = 0; i < 8; i++) {
            int idx = t + i * 128;
            int r = idx >> 4, c4 = idx & 15;
            float4 v = *(const float4*)&x[(size_t)(row0 + r) * FIN + k0 + c4 * 4];
            v.x = f2tf32(v.x); v.y = f2tf32(v.y); v.z = f2tf32(v.z); v.w = f2tf32(v.w);
            *(float4*)&Xs[r][c4 * 4] = v;
            float4 w = *(const float4*)&W[(size_t)(k0 + r) * HD + col0 + c4 * 4];
            w.x = f2tf32(w.x); w.y = f2tf32(w.y); w.z = f2tf32(w.z); w.w = f2tf32(w.w);
            *(float4*)&Ws[r][c4 * 4] = w;
        }
        __syncthreads();
        #pragma unroll
        for (int kk = 0; kk < 8; kk++) {
            wmma::fragment<wmma::matrix_a, 16, 16, 8, wmma::precision::tf32, wmma::row_major> a[2];
            wmma::fragment<wmma::matrix_b, 16, 16, 8, wmma::precision::tf32, wmma::row_major> bfr[2];
            #pragma unroll
            for (int i = 0; i < 2; i++)
                wmma::load_matrix_sync(a[i], &Xs[warp_m + 16 * i][kk * 8], 72);
            #pragma unroll
            for (int j = 0; j < 2; j++)
                wmma::load_matrix_sync(bfr[j], &Ws[kk * 8][warp_n + 16 * j], 72);
            #pragma unroll
            for (int i = 0; i < 2; i++)
                #pragma unroll
                for (int j = 0; j < 2; j++)
                    wmma::mma_sync(c[i][j], a[i], bfr[j], c[i][j]);
        }
        __syncthreads();
    }

    __shared__ float Stage[64][72];
    #pragma unroll
    for (int i = 0; i < 2; i++)
        #pragma unroll
        for (int j = 0; j < 2; j++)
            wmma::store_matrix_sync(&Stage[warp_m + 16 * i][warp_n + 16 * j], c[i][j], 72,
                                    wmma::mem_row_major);
    __syncthreads();
    #pragma unroll
    for (int i = 0; i < 8; i++) {
        int idx = t + i * 128;
        int r = idx >> 4, c4 = idx & 15;
        float4 v = *(float4*)&Stage[r][c4 * 4];
        float4 bb = *(const float4*)&bias[col0 + c4 * 4];
        v.x += bb.x; v.y += bb.y; v.z += bb.z; v.w += bb.w;
        *(float4*)&g_h[(size_t)(row0 + r) * HD + col0 + c4 * 4] = v;
    }
}

// ---------------------------------------------------------------------------
// K2: fused scores -> mask -> exp -> (store e) -> O accumulate -> normalize
// grid (N/64, B*H), 128 threads. K tile == V tile (shared projection).
// Dynamic smem: Qs[64*72] Ks[64*72] Es[64*72] + mask words[128]
// ---------------------------------------------------------------------------
__global__ void k_fused() {
    extern __shared__ float sm[];
    float* Qs = sm;                    // 64*72
    float* Ks = sm + 64 * 72;
    float* Es = sm + 2 * 64 * 72;
    unsigned* mw = (unsigned*)(sm + 3 * 64 * 72);   // 128 words

    const int t = threadIdx.x;
    const int wid = t >> 5;
    const int warp_m = (wid & 1) * 32;
    const int warp_n = (wid >> 1) * 32;
    const int row0 = blockIdx.x * 64;
    const int bh = blockIdx.y;
    const int b = bh >> 3, hh = bh & 7;

    const float* Hbase = g_h + (size_t)b * NN * HD + hh * DD;
    const unsigned* mbase = g_mask + ((size_t)b * NN + row0) * NW;

    const int r_ew = t >> 1;          // elementwise row this thread owns
    const int half = t & 1;
    const int c0 = half * 32;

    // load Q tile (tf32)
    #pragma unroll
    for (int i = 0; i < 8; i++) {
        int idx = t + i * 128;
        int r = idx >> 4, c4 = idx & 15;
        float4 q = *(const float4*)&Hbase[(size_t)(row0 + r) * HD + c4 * 4];
        q.x = f2tf32(q.x); q.y = f2tf32(q.y); q.z = f2tf32(q.z); q.w = f2tf32(q.w);
        *(float4*)&Qs[r * 72 + c4 * 4] = q;
    }

    wmma::fragment<wmma::accumulator, 16, 16, 8, float> Oacc[2][2];
    #pragma unroll
    for (int i = 0; i < 2; i++)
        #pragma unroll
        for (int j = 0; j < 2; j++) wmma::fill_fragment(Oacc[i][j], 0.f);

    float rs_acc = 0.f;
    __syncthreads();

    for (int m0 = 0; m0 < NN; m0 += 64) {
        // load K/V tile (tf32) + mask words
        #pragma unroll
        for (int i = 0; i < 8; i++) {
            int idx = t + i * 128;
            int r = idx >> 4, c4 = idx & 15;
            float4 k = *(const float4*)&Hbase[(size_t)(m0 + r) * HD + c4 * 4];
            k.x = f2tf32(k.x); k.y = f2tf32(k.y); k.z = f2tf32(k.z); k.w = f2tf32(k.w);
            *(float4*)&Ks[r * 72 + c4 * 4] = k;
        }
        mw[t] = mbase[(size_t)r_ew * NW + (m0 >> 5) + half];
        __syncthreads();

        // S = Q Kᵀ
        wmma::fragment<wmma::accumulator, 16, 16, 8, float> Sacc[2][2];
        #pragma unroll
        for (int i = 0; i < 2; i++)
            #pragma unroll
            for (int j = 0; j < 2; j++) wmma::fill_fragment(Sacc[i][j], 0.f);
        #pragma unroll
        for (int kk = 0; kk < 8; kk++) {
            wmma::fragment<wmma::matrix_a, 16, 16, 8, wmma::precision::tf32, wmma::row_major> a[2];
            wmma::fragment<wmma::matrix_b, 16, 16, 8, wmma::precision::tf32, wmma::col_major> bfr[2];
            #pragma unroll
            for (int i = 0; i < 2; i++)
                wmma::load_matrix_sync(a[i], &Qs[(warp_m + 16 * i) * 72 + kk * 8], 72);
            #pragma unroll
            for (int j = 0; j < 2; j++)
                wmma::load_matrix_sync(bfr[j], &Ks[(warp_n + 16 * j) * 72 + kk * 8], 72);
            #pragma unroll
            for (int i = 0; i < 2; i++)
                #pragma unroll
                for (int j = 0; j < 2; j++)
                    wmma::mma_sync(Sacc[i][j], a[i], bfr[j], Sacc[i][j]);
        }
        #pragma unroll
        for (int i = 0; i < 2; i++)
            #pragma unroll
            for (int j = 0; j < 2; j++)
                wmma::store_matrix_sync(&Es[(warp_m + 16 * i) * 72 + warp_n + 16 * j],
                                        Sacc[i][j], 72, wmma::mem_row_major);
        __syncthreads();

        // mask + exp + rowsum + store e (tf32-rounded) to smem & gmem
        {
            unsigned word = mw[r_ew * 2 + half];
            float* erow = &Es[r_ew * 72 + c0];
            float* grow = &g_S[((size_t)bh * NN + row0 + r_ew) * NN + m0 + c0];
            float lsum = 0.f;
            #pragma unroll
            for (int i = 0; i < 8; i++) {
                float4 s4 = *(float4*)&erow[i * 4];
                float4 e4;
                e4.x = ((word >> (i * 4 + 0)) & 1u) ? f2tf32(__expf(s4.x * SCALE)) : 0.f;
                e4.y = ((word >> (i * 4 + 1)) & 1u) ? f2tf32(__expf(s4.y * SCALE)) : 0.f;
                e4.z = ((word >> (i * 4 + 2)) & 1u) ? f2tf32(__expf(s4.z * SCALE)) : 0.f;
                e4.w = ((word >> (i * 4 + 3)) & 1u) ? f2tf32(__expf(s4.w * SCALE)) : 0.f;
                lsum += (e4.x + e4.y) + (e4.z + e4.w);
                *(float4*)&erow[i * 4] = e4;
                *(float4*)&grow[i * 4] = e4;
            }
            rs_acc += lsum + __shfl_xor_sync(0xffffffffu, lsum, 1);
        }
        __syncthreads();

        // O += E V   (V tile == K tile, row-major)
        #pragma unroll
        for (int kk = 0; kk < 8; kk++) {
            wmma::fragment<wmma::matrix_a, 16, 16, 8, wmma::precision::tf32, wmma::row_major> a[2];
            wmma::fragment<wmma::matrix_b, 16, 16, 8, wmma::precision::tf32, wmma::row_major> bfr[2];
            #pragma unroll
            for (int i = 0; i < 2; i++)
                wmma::load_matrix_sync(a[i], &Es[(warp_m + 16 * i) * 72 + kk * 8], 72);
            #pragma unroll
            for (int j = 0; j < 2; j++)
                wmma::load_matrix_sync(bfr[j], &Ks[(kk * 8) * 72 + warp_n + 16 * j], 72);
            #pragma unroll
            for (int i = 0; i < 2; i++)
                #pragma unroll
                for (int j = 0; j < 2; j++)
                    wmma::mma_sync(Oacc[i][j], a[i], bfr[j], Oacc[i][j]);
        }
        __syncthreads();
    }

    // epilogue: stage O, normalize by rowsum, write out
    #pragma unroll
    for (int i = 0; i < 2; i++)
        #pragma unroll
        for (int j = 0; j < 2; j++)
            wmma::store_matrix_sync(&Qs[(warp_m + 16 * i) * 72 + warp_n + 16 * j],
                                    Oacc[i][j], 72, wmma::mem_row_major);
    __syncthreads();

    if (half == 0) g_rowsum[(size_t)bh * NN + row0 + r_ew] = rs_acc;
    const float invr = 1.f / rs_acc;
    float* orow = &g_O[((size_t)b * NN + row0 + r_ew) * HD + hh * DD + c0];
    #pragma unroll
    for (int i = 0; i < 8; i++) {
        float4 o4 = *(float4*)&Qs[r_ew * 72 + c0 + i * 4];
        o4.x *= invr; o4.y *= invr; o4.z *= invr; o4.w *= invr;
        *(float4*)&orow[i * 4] = o4;
    }
}

// ---------------------------------------------------------------------------
// K3: mean over heads of p = e / rowsum  -> out_mean
// ---------------------------------------------------------------------------
__global__ void k_mean(float* __restrict__ out_mean) {
    __shared__ float inv[HH];
    const int row = blockIdx.x;           // b*N + n
    const int b = row >> 11;
    const int n = row & (NN - 1);
    const int t = threadIdx.x;            // 256

    if (t < HH) inv[t] = 0.125f / g_rowsum[(size_t)(b * HH + t) * NN + n];
    __syncthreads();

    float* mrow = out_mean + (size_t)row * NN;
    #pragma unroll
    for (int c4 = t; c4 < NN / 4; c4 += 256) {
        float4 acc = make_float4(0.f, 0.f, 0.f, 0.f);
        #pragma unroll
        for (int h = 0; h < HH; h++) {
            const float4 e4 = *(const float4*)&g_S[((size_t)(b * HH + h) * NN + n) * NN + c4 * 4];
            float iv = inv[h];
            acc.x += e4.x * iv; acc.y += e4.y * iv;
            acc.z += e4.z * iv; acc.w += e4.w * iv;
        }
        *(float4*)&mrow[c4 * 4] = acc;
    }
}

// ---------------------------------------------------------------------------
// K5: LayerNorm -> out
// ---------------------------------------------------------------------------
__global__ void k_ln(const float* __restrict__ gamma, const float* __restrict__ beta,
                     float* __restrict__ out) {
    __shared__ float red[128];
    __shared__ float red2[128];

    const int row = blockIdx.x;
    const int t = threadIdx.x;
    const float* v = g_O + (size_t)row * HD;

    float s = 0.f, s2 = 0.f;
    float vals[4];
    #pragma unroll
    for (int i = 0; i < 4; i++) {
        vals[i] = v[t + i * 128];
        s += vals[i];
        s2 += vals[i] * vals[i];
    }
    red[t] = s; red2[t] = s2;
    __syncthreads();
    for (int st = 64; st > 0; st >>= 1) {
        if (t < st) { red[t] += red[t + st]; red2[t] += red2[t + st]; }
        __syncthreads();
    }
    const float mu = red[0] * (1.f / HD);
    const float var = red2[0] * (1.f / HD) - mu * mu;
    const float rstd = rsqrtf(var + EPS);

    float* orow = out + (size_t)row * HD;
    #pragma unroll
    for (int i = 0; i < 4; i++) {
        int c = t + i * 128;
        orow[c] = (vals[i] - mu) * rstd * gamma[c] + beta[c];
    }
}

// ---------------------------------------------------------------------------
extern "C" void kernel_launch(void* const* d_in, const int* in_sizes, int n_in,
                              void* d_out, int out_size) {
    const float* x     = (const float*)d_in[0];
    const int*   adj   = (const int*)d_in[1];
    const float* W_w   = (const float*)d_in[2];
    const float* W_b   = (const float*)d_in[3];
    const float* gamma = (const float*)d_in[4];
    const float* beta  = (const float*)d_in[5];
    float* out = (float*)d_out;
    float* out_mean = out + (size_t)BB * NN * HD;

    const int SMEMB = (3 * 64 * 72) * 4 + 128 * 4;   // 55808 B
    cudaFuncSetAttribute(k_fused, cudaFuncAttributeMaxDynamicSharedMemorySize, SMEMB);

    k_pack<<<BB * NN, 256>>>(adj);
    k_proj<<<dim3(HD / 64, (BB * NN) / 64), 128>>>(x, W_w, W_b);
    k_fused<<<dim3(NN / 64, BB * HH), 128, SMEMB>>>();
    k_mean<<<BB * NN, 256>>>(out_mean);
    k_ln<<<BB * NN, 128>>>(gamma, beta, out);
}

// round 4
// speedup vs baseline: 2.1085x; 1.0848x over previous
#include <cuda_runtime.h>
#include <cuda_bf16.h>
#include <math_constants.h>
#include <mma.h>

using namespace nvcuda;

#define BB 2
#define NN 2048
#define HH 8
#define DD 64
#define FIN 512
#define HD 512
#define EPS 1e-5f
#define SCALE 0.125f
#define NW (NN / 32)

// Device scratch
__device__ float g_h[BB * NN * HD];
__device__ float g_S[(size_t)BB * HH * NN * NN];       // unnormalized exp values
__device__ float g_O[BB * NN * HD];
__device__ float g_rowsum[BB * HH * NN];
__device__ unsigned g_mask[(size_t)BB * NN * NW];

__device__ __forceinline__ float f2tf32(float x) {
    float r;
    asm("cvt.rna.tf32.f32 %0, %1;" : "=f"(r) : "f"(x));
    return r;
}

// ---------------------------------------------------------------------------
// K0: pack adj -> bitmask
// ---------------------------------------------------------------------------
__global__ void k_pack(const int* __restrict__ adj) {
    const int row = blockIdx.x;
    const int t = threadIdx.x;
    const int warp = t >> 5, lane = t & 31;
    const int* arow = adj + (size_t)row * NN;
    #pragma unroll
    for (int j = warp; j < NW; j += 8) {
        unsigned bit = (arow[j * 32 + lane] != 0) ? 1u : 0u;
        unsigned word = __ballot_sync(0xffffffffu, bit);
        if (lane == 0) g_mask[(size_t)row * NW + j] = word;
    }
}

// ---------------------------------------------------------------------------
// K1: h = x @ W + b   (tf32 wmma)
// ---------------------------------------------------------------------------
__global__ void k_proj(const float* __restrict__ x, const float* __restrict__ W,
                       const float* __restrict__ bias) {
    __shared__ float Xs[64][72];
    __shared__ float Ws[64][72];

    const int t = threadIdx.x;
    const int wid = t >> 5;
    const int warp_m = (wid & 1) * 32;
    const int warp_n = (wid >> 1) * 32;
    const int row0 = blockIdx.y * 64;
    const int col0 = blockIdx.x * 64;

    wmma::fragment<wmma::accumulator, 16, 16, 8, float> c[2][2];
    #pragma unroll
    for (int i = 0; i < 2; i++)
        #pragma unroll
        for (int j = 0; j < 2; j++) wmma::fill_fragment(c[i][j], 0.f);

    for (int k0 = 0; k0 < FIN; k0 += 64) {
        #pragma unroll
        for (int i = 0; i < 8; i++) {
            int idx = t + i * 128;
            int r = idx >> 4, c4 = idx & 15;
            float4 v = *(const float4*)&x[(size_t)(row0 + r) * FIN + k0 + c4 * 4];
            v.x = f2tf32(v.x); v.y = f2tf32(v.y); v.z = f2tf32(v.z); v.w = f2tf32(v.w);
            *(float4*)&Xs[r][c4 * 4] = v;
            float4 w = *(const float4*)&W[(size_t)(k0 + r) * HD + col0 + c4 * 4];
            w.x = f2tf32(w.x); w.y = f2tf32(w.y); w.z = f2tf32(w.z); w.w = f2tf32(w.w);
            *(float4*)&Ws[r][c4 * 4] = w;
        }
        __syncthreads();
        #pragma unroll
        for (int kk = 0; kk < 8; kk++) {
            wmma::fragment<wmma::matrix_a, 16, 16, 8, wmma::precision::tf32, wmma::row_major> a[2];
            wmma::fragment<wmma::matrix_b, 16, 16, 8, wmma::precision::tf32, wmma::row_major> bfr[2];
            #pragma unroll
            for (int i = 0; i < 2; i++)
                wmma::load_matrix_sync(a[i], &Xs[warp_m + 16 * i][kk * 8], 72);
            #pragma unroll
            for (int j = 0; j < 2; j++)
                wmma::load_matrix_sync(bfr[j], &Ws[kk * 8][warp_n + 16 * j], 72);
            #pragma unroll
            for (int i = 0; i < 2; i++)
                #pragma unroll
                for (int j = 0; j < 2; j++)
                    wmma::mma_sync(c[i][j], a[i], bfr[j], c[i][j]);
        }
        __syncthreads();
    }

    __shared__ float Stage[64][72];
    #pragma unroll
    for (int i = 0; i < 2; i++)
        #pragma unroll
        for (int j = 0; j < 2; j++)
            wmma::store_matrix_sync(&Stage[warp_m + 16 * i][warp_n + 16 * j], c[i][j], 72,
                                    wmma::mem_row_major);
    __syncthreads();
    #pragma unroll
    for (int i = 0; i < 8; i++) {
        int idx = t + i * 128;
        int r = idx >> 4, c4 = idx & 15;
        float4 v = *(float4*)&Stage[r][c4 * 4];
        float4 bb = *(const float4*)&bias[col0 + c4 * 4];
        v.x += bb.x; v.y += bb.y; v.z += bb.z; v.w += bb.w;
        *(float4*)&g_h[(size_t)(row0 + r) * HD + col0 + c4 * 4] = v;
    }
}

// ---------------------------------------------------------------------------
// K2: fused scores -> mask -> exp -> (store e) -> O accumulate -> normalize
// CTA tile: 128 rows x 64 m-cols. 256 threads, 8 warps (4 in M x 2 in N).
// smem: Qs[128*72] Ks[64*72] Es[128*72] + mask[256]
// ---------------------------------------------------------------------------
__global__ __launch_bounds__(256, 2) void k_fused() {
    extern __shared__ float sm[];
    float* Qs = sm;                         // 128*72
    float* Ks = sm + 128 * 72;              // 64*72
    float* Es = sm + 128 * 72 + 64 * 72;    // 128*72
    unsigned* mw = (unsigned*)(sm + (128 + 64 + 128) * 72);

    const int t = threadIdx.x;
    const int wid = t >> 5;
    const int warp_m = (wid & 3) * 32;     // 0..96
    const int warp_n = (wid >> 2) * 32;    // 0 or 32
    const int row0 = blockIdx.x * 128;
    const int bh = blockIdx.y;
    const int b = bh >> 3, hh = bh & 7;

    const float* Hbase = g_h + (size_t)b * NN * HD + hh * DD;
    const unsigned* mbase = g_mask + ((size_t)b * NN + row0) * NW;

    const int r_ew = t >> 1;               // 0..127
    const int half = t & 1;
    const int c0 = half * 32;

    // load Q tile 128x64 (tf32)
    #pragma unroll
    for (int i = 0; i < 8; i++) {
        int idx = t + i * 256;
        int r = idx >> 4, c4 = idx & 15;
        float4 q = *(const float4*)&Hbase[(size_t)(row0 + r) * HD + c4 * 4];
        q.x = f2tf32(q.x); q.y = f2tf32(q.y); q.z = f2tf32(q.z); q.w = f2tf32(q.w);
        *(float4*)&Qs[r * 72 + c4 * 4] = q;
    }

    wmma::fragment<wmma::accumulator, 16, 16, 8, float> Oacc[2][2];
    #pragma unroll
    for (int i = 0; i < 2; i++)
        #pragma unroll
        for (int j = 0; j < 2; j++) wmma::fill_fragment(Oacc[i][j], 0.f);

    float rs_acc = 0.f;
    __syncthreads();

    for (int m0 = 0; m0 < NN; m0 += 64) {
        // load K/V tile 64x64 (tf32) + mask words
        #pragma unroll
        for (int i = 0; i < 4; i++) {
            int idx = t + i * 256;
            int r = idx >> 4, c4 = idx & 15;
            float4 k = *(const float4*)&Hbase[(size_t)(m0 + r) * HD + c4 * 4];
            k.x = f2tf32(k.x); k.y = f2tf32(k.y); k.z = f2tf32(k.z); k.w = f2tf32(k.w);
            *(float4*)&Ks[r * 72 + c4 * 4] = k;
        }
        mw[t] = mbase[(size_t)r_ew * NW + (m0 >> 5) + half];
        __syncthreads();

        // S = Q Kᵀ  (128x64)
        wmma::fragment<wmma::accumulator, 16, 16, 8, float> Sacc[2][2];
        #pragma unroll
        for (int i = 0; i < 2; i++)
            #pragma unroll
            for (int j = 0; j < 2; j++) wmma::fill_fragment(Sacc[i][j], 0.f);
        #pragma unroll
        for (int kk = 0; kk < 8; kk++) {
            wmma::fragment<wmma::matrix_a, 16, 16, 8, wmma::precision::tf32, wmma::row_major> a[2];
            wmma::fragment<wmma::matrix_b, 16, 16, 8, wmma::precision::tf32, wmma::col_major> bfr[2];
            #pragma unroll
            for (int i = 0; i < 2; i++)
                wmma::load_matrix_sync(a[i], &Qs[(warp_m + 16 * i) * 72 + kk * 8], 72);
            #pragma unroll
            for (int j = 0; j < 2; j++)
                wmma::load_matrix_sync(bfr[j], &Ks[(warp_n + 16 * j) * 72 + kk * 8], 72);
            #pragma unroll
            for (int i = 0; i < 2; i++)
                #pragma unroll
                for (int j = 0; j < 2; j++)
                    wmma::mma_sync(Sacc[i][j], a[i], bfr[j], Sacc[i][j]);
        }
        #pragma unroll
        for (int i = 0; i < 2; i++)
            #pragma unroll
            for (int j = 0; j < 2; j++)
                wmma::store_matrix_sync(&Es[(warp_m + 16 * i) * 72 + warp_n + 16 * j],
                                        Sacc[i][j], 72, wmma::mem_row_major);
        __syncthreads();

        // mask + exp + rowsum; write e to smem and stream to gmem
        {
            unsigned word = mw[r_ew * 2 + half];
            float* erow = &Es[r_ew * 72 + c0];
            float* grow = &g_S[((size_t)bh * NN + row0 + r_ew) * NN + m0 + c0];
            float lsum = 0.f;
            #pragma unroll
            for (int i = 0; i < 8; i++) {
                float4 s4 = *(float4*)&erow[i * 4];
                float4 e4;
                e4.x = ((word >> (i * 4 + 0)) & 1u) ? f2tf32(__expf(s4.x * SCALE)) : 0.f;
                e4.y = ((word >> (i * 4 + 1)) & 1u) ? f2tf32(__expf(s4.y * SCALE)) : 0.f;
                e4.z = ((word >> (i * 4 + 2)) & 1u) ? f2tf32(__expf(s4.z * SCALE)) : 0.f;
                e4.w = ((word >> (i * 4 + 3)) & 1u) ? f2tf32(__expf(s4.w * SCALE)) : 0.f;
                lsum += (e4.x + e4.y) + (e4.z + e4.w);
                *(float4*)&erow[i * 4] = e4;
                __stcs((float4*)&grow[i * 4], e4);
            }
            rs_acc += lsum + __shfl_xor_sync(0xffffffffu, lsum, 1);
        }
        __syncthreads();

        // O += E V   (V tile == K tile)
        #pragma unroll
        for (int kk = 0; kk < 8; kk++) {
            wmma::fragment<wmma::matrix_a, 16, 16, 8, wmma::precision::tf32, wmma::row_major> a[2];
            wmma::fragment<wmma::matrix_b, 16, 16, 8, wmma::precision::tf32, wmma::row_major> bfr[2];
            #pragma unroll
            for (int i = 0; i < 2; i++)
                wmma::load_matrix_sync(a[i], &Es[(warp_m + 16 * i) * 72 + kk * 8], 72);
            #pragma unroll
            for (int j = 0; j < 2; j++)
                wmma::load_matrix_sync(bfr[j], &Ks[(kk * 8) * 72 + warp_n + 16 * j], 72);
            #pragma unroll
            for (int i = 0; i < 2; i++)
                #pragma unroll
                for (int j = 0; j < 2; j++)
                    wmma::mma_sync(Oacc[i][j], a[i], bfr[j], Oacc[i][j]);
        }
        __syncthreads();
    }

    // epilogue: stage O into Qs, normalize, write out
    #pragma unroll
    for (int i = 0; i < 2; i++)
        #pragma unroll
        for (int j = 0; j < 2; j++)
            wmma::store_matrix_sync(&Qs[(warp_m + 16 * i) * 72 + warp_n + 16 * j],
                                    Oacc[i][j], 72, wmma::mem_row_major);
    __syncthreads();

    if (half == 0) g_rowsum[(size_t)bh * NN + row0 + r_ew] = rs_acc;
    const float invr = 1.f / rs_acc;
    float* orow = &g_O[((size_t)b * NN + row0 + r_ew) * HD + hh * DD + c0];
    #pragma unroll
    for (int i = 0; i < 8; i++) {
        float4 o4 = *(float4*)&Qs[r_ew * 72 + c0 + i * 4];
        o4.x *= invr; o4.y *= invr; o4.z *= invr; o4.w *= invr;
        *(float4*)&orow[i * 4] = o4;
    }
}

// ---------------------------------------------------------------------------
// K3: mean over heads of p = e / rowsum  -> out_mean
// ---------------------------------------------------------------------------
__global__ void k_mean(float* __restrict__ out_mean) {
    __shared__ float inv[HH];
    const int row = blockIdx.x;
    const int b = row >> 11;
    const int n = row & (NN - 1);
    const int t = threadIdx.x;

    if (t < HH) inv[t] = 0.125f / g_rowsum[(size_t)(b * HH + t) * NN + n];
    __syncthreads();

    float* mrow = out_mean + (size_t)row * NN;
    #pragma unroll
    for (int c4 = t; c4 < NN / 4; c4 += 256) {
        float4 acc = make_float4(0.f, 0.f, 0.f, 0.f);
        #pragma unroll
        for (int h = 0; h < HH; h++) {
            const float4 e4 = __ldcs((const float4*)&g_S[((size_t)(b * HH + h) * NN + n) * NN + c4 * 4]);
            float iv = inv[h];
            acc.x += e4.x * iv; acc.y += e4.y * iv;
            acc.z += e4.z * iv; acc.w += e4.w * iv;
        }
        *(float4*)&mrow[c4 * 4] = acc;
    }
}

// ---------------------------------------------------------------------------
// K5: LayerNorm -> out
// ---------------------------------------------------------------------------
__global__ void k_ln(const float* __restrict__ gamma, const float* __restrict__ beta,
                     float* __restrict__ out) {
    __shared__ float red[128];
    __shared__ float red2[128];

    const int row = blockIdx.x;
    const int t = threadIdx.x;
    const float* v = g_O + (size_t)row * HD;

    float s = 0.f, s2 = 0.f;
    float vals[4];
    #pragma unroll
    for (int i = 0; i < 4; i++) {
        vals[i] = v[t + i * 128];
        s += vals[i];
        s2 += vals[i] * vals[i];
    }
    red[t] = s; red2[t] = s2;
    __syncthreads();
    for (int st = 64; st > 0; st >>= 1) {
        if (t < st) { red[t] += red[t + st]; red2[t] += red2[t + st]; }
        __syncthreads();
    }
    const float mu = red[0] * (1.f / HD);
    const float var = red2[0] * (1.f / HD) - mu * mu;
    const float rstd = rsqrtf(var + EPS);

    float* orow = out + (size_t)row * HD;
    #pragma unroll
    for (int i = 0; i < 4; i++) {
        int c = t + i * 128;
        orow[c] = (vals[i] - mu) * rstd * gamma[c] + beta[c];
    }
}

// ---------------------------------------------------------------------------
extern "C" void kernel_launch(void* const* d_in, const int* in_sizes, int n_in,
                              void* d_out, int out_size) {
    const float* x     = (const float*)d_in[0];
    const int*   adj   = (const int*)d_in[1];
    const float* W_w   = (const float*)d_in[2];
    const float* W_b   = (const float*)d_in[3];
    const float* gamma = (const float*)d_in[4];
    const float* beta  = (const float*)d_in[5];
    float* out = (float*)d_out;
    float* out_mean = out + (size_t)BB * NN * HD;

    const int SMEMB = (128 + 64 + 128) * 72 * 4 + 256 * 4;   // 93184 B
    cudaFuncSetAttribute(k_fused, cudaFuncAttributeMaxDynamicSharedMemorySize, SMEMB);

    k_pack<<<BB * NN, 256>>>(adj);
    k_proj<<<dim3(HD / 64, (BB * NN) / 64), 128>>>(x, W_w, W_b);
    k_fused<<<dim3(NN / 128, BB * HH), 256, SMEMB>>>();
    k_mean<<<BB * NN, 256>>>(out_mean);
    k_ln<<<BB * NN, 128>>>(gamma, beta, out);
}

// round 5
// speedup vs baseline: 2.9724x; 1.4097x over previous
#include <cuda_runtime.h>
#include <cuda_bf16.h>
#include <math_constants.h>
#include <mma.h>

using namespace nvcuda;

#define BB 2
#define NN 2048
#define HH 8
#define DD 64
#define FIN 512
#define HD 512
#define EPS 1e-5f
#define SCALE 0.125f
#define NW (NN / 32)

// Device scratch
__device__ float g_h[BB * NN * HD];
__device__ float g_S[(size_t)BB * HH * NN * NN];       // unnormalized exp values
__device__ float g_O[BB * NN * HD];
__device__ float g_rowsum[BB * HH * NN];
__device__ unsigned g_mask[(size_t)BB * NN * NW];

__device__ __forceinline__ float f2tf32(float x) {
    float r;
    asm("cvt.rna.tf32.f32 %0, %1;" : "=f"(r) : "f"(x));
    return r;
}

__device__ __forceinline__ void mma_tf32(float d[4], unsigned a0, unsigned a1,
                                         unsigned a2, unsigned a3,
                                         unsigned b0, unsigned b1) {
    asm volatile(
        "mma.sync.aligned.m16n8k8.row.col.f32.tf32.tf32.f32 "
        "{%0,%1,%2,%3}, {%4,%5,%6,%7}, {%8,%9}, {%0,%1,%2,%3};"
        : "+f"(d[0]), "+f"(d[1]), "+f"(d[2]), "+f"(d[3])
        : "r"(a0), "r"(a1), "r"(a2), "r"(a3), "r"(b0), "r"(b1));
}

// ---------------------------------------------------------------------------
// K0: pack adj -> bitmask
// ---------------------------------------------------------------------------
__global__ void k_pack(const int* __restrict__ adj) {
    const int row = blockIdx.x;
    const int t = threadIdx.x;
    const int warp = t >> 5, lane = t & 31;
    const int* arow = adj + (size_t)row * NN;
    #pragma unroll
    for (int j = warp; j < NW; j += 8) {
        unsigned bit = (arow[j * 32 + lane] != 0) ? 1u : 0u;
        unsigned word = __ballot_sync(0xffffffffu, bit);
        if (lane == 0) g_mask[(size_t)row * NW + j] = word;
    }
}

// ---------------------------------------------------------------------------
// K1: h = x @ W + b   (tf32 wmma); outputs rounded to tf32
// ---------------------------------------------------------------------------
__global__ void k_proj(const float* __restrict__ x, const float* __restrict__ W,
                       const float* __restrict__ bias) {
    __shared__ float Xs[64][72];
    __shared__ float Ws[64][72];

    const int t = threadIdx.x;
    const int wid = t >> 5;
    const int warp_m = (wid & 1) * 32;
    const int warp_n = (wid >> 1) * 32;
    const int row0 = blockIdx.y * 64;
    const int col0 = blockIdx.x * 64;

    wmma::fragment<wmma::accumulator, 16, 16, 8, float> c[2][2];
    #pragma unroll
    for (int i = 0; i < 2; i++)
        #pragma unroll
        for (int j = 0; j < 2; j++) wmma::fill_fragment(c[i][j], 0.f);

    for (int k0 = 0; k0 < FIN; k0 += 64) {
        #pragma unroll
        for (int i = 0; i < 8; i++) {
            int idx = t + i * 128;
            int r = idx >> 4, c4 = idx & 15;
            float4 v = *(const float4*)&x[(size_t)(row0 + r) * FIN + k0 + c4 * 4];
            v.x = f2tf32(v.x); v.y = f2tf32(v.y); v.z = f2tf32(v.z); v.w = f2tf32(v.w);
            *(float4*)&Xs[r][c4 * 4] = v;
            float4 w = *(const float4*)&W[(size_t)(k0 + r) * HD + col0 + c4 * 4];
            w.x = f2tf32(w.x); w.y = f2tf32(w.y); w.z = f2tf32(w.z); w.w = f2tf32(w.w);
            *(float4*)&Ws[r][c4 * 4] = w;
        }
        __syncthreads();
        #pragma unroll
        for (int kk = 0; kk < 8; kk++) {
            wmma::fragment<wmma::matrix_a, 16, 16, 8, wmma::precision::tf32, wmma::row_major> a[2];
            wmma::fragment<wmma::matrix_b, 16, 16, 8, wmma::precision::tf32, wmma::row_major> bfr[2];
            #pragma unroll
            for (int i = 0; i < 2; i++)
                wmma::load_matrix_sync(a[i], &Xs[warp_m + 16 * i][kk * 8], 72);
            #pragma unroll
            for (int j = 0; j < 2; j++)
                wmma::load_matrix_sync(bfr[j], &Ws[kk * 8][warp_n + 16 * j], 72);
            #pragma unroll
            for (int i = 0; i < 2; i++)
                #pragma unroll
                for (int j = 0; j < 2; j++)
                    wmma::mma_sync(c[i][j], a[i], bfr[j], c[i][j]);
        }
        __syncthreads();
    }

    __shared__ float Stage[64][72];
    #pragma unroll
    for (int i = 0; i < 2; i++)
        #pragma unroll
        for (int j = 0; j < 2; j++)
            wmma::store_matrix_sync(&Stage[warp_m + 16 * i][warp_n + 16 * j], c[i][j], 72,
                                    wmma::mem_row_major);
    __syncthreads();
    #pragma unroll
    for (int i = 0; i < 8; i++) {
        int idx = t + i * 128;
        int r = idx >> 4, c4 = idx & 15;
        float4 v = *(float4*)&Stage[r][c4 * 4];
        float4 bb = *(const float4*)&bias[col0 + c4 * 4];
        // round to tf32 at the source: k_fused then consumes raw bits
        v.x = f2tf32(v.x + bb.x); v.y = f2tf32(v.y + bb.y);
        v.z = f2tf32(v.z + bb.z); v.w = f2tf32(v.w + bb.w);
        *(float4*)&g_h[(size_t)(row0 + r) * HD + col0 + c4 * 4] = v;
    }
}

// ---------------------------------------------------------------------------
// K2: register-resident fused attention (raw mma.sync tf32)
// CTA: 512 threads / 16 warps; each warp owns 16 q-rows -> 256-row tile.
// m-loop over 2048 in 64-chunks; K/V tile double-buffered via cp.async.
// ---------------------------------------------------------------------------
#define KSTR 68   // smem tile stride (floats)

__global__ __launch_bounds__(512, 1) void k_fused() {
    __shared__ float buf[2][64 * KSTR];

    const int t = threadIdx.x;
    const int lane = t & 31;
    const int wid = t >> 5;                 // 0..15
    const int g = lane >> 2;                // 0..7
    const int q = lane & 3;                 // 0..3
    const int row0 = blockIdx.x * 256;
    const int bh = blockIdx.y;
    const int b = bh >> 3, hh = bh & 7;

    const float* Hb = g_h + (size_t)b * NN * HD + hh * DD;
    const int r_lo = row0 + wid * 16 + g;   // this thread's low row
    const int r_hi = r_lo + 8;

    // --- prefetch K/V tile 0 via cp.async ---
    {
        #pragma unroll
        for (int k = 0; k < 2; k++) {
            int c = t + k * 512;             // 0..1023
            int r = c >> 4, seg = c & 15;
            unsigned dst = (unsigned)__cvta_generic_to_shared(&buf[0][r * KSTR + seg * 4]);
            const float* src = &Hb[(size_t)r * HD + seg * 4];
            asm volatile("cp.async.ca.shared.global [%0], [%1], 16;" :: "r"(dst), "l"(src));
        }
        asm volatile("cp.async.commit_group;");
    }

    // --- load Q fragments (g_h already tf32-rounded) ---
    unsigned Qa[8][4];
    #pragma unroll
    for (int kc = 0; kc < 8; kc++) {
        Qa[kc][0] = __float_as_uint(Hb[(size_t)r_lo * HD + 8 * kc + q]);
        Qa[kc][1] = __float_as_uint(Hb[(size_t)r_hi * HD + 8 * kc + q]);
        Qa[kc][2] = __float_as_uint(Hb[(size_t)r_lo * HD + 8 * kc + q + 4]);
        Qa[kc][3] = __float_as_uint(Hb[(size_t)r_hi * HD + 8 * kc + q + 4]);
    }

    float Oa[8][4];
    #pragma unroll
    for (int f = 0; f < 8; f++)
        #pragma unroll
        for (int e = 0; e < 4; e++) Oa[f][e] = 0.f;
    float rs_lo = 0.f, rs_hi = 0.f;

    const unsigned* mrow_lo = &g_mask[((size_t)b * NN + r_lo) * NW];
    const unsigned* mrow_hi = &g_mask[((size_t)b * NN + r_hi) * NW];
    float* Srow_lo = &g_S[((size_t)bh * NN + r_lo) * NN];
    float* Srow_hi = &g_S[((size_t)bh * NN + r_hi) * NN];

    for (int it = 0; it < 32; it++) {
        const int m0 = it * 64;
        asm volatile("cp.async.wait_group 0;");
        __syncthreads();

        if (it < 31) {
            #pragma unroll
            for (int k = 0; k < 2; k++) {
                int c = t + k * 512;
                int r = c >> 4, seg = c & 15;
                unsigned dst = (unsigned)__cvta_generic_to_shared(
                    &buf[(it + 1) & 1][r * KSTR + seg * 4]);
                const float* src = &Hb[(size_t)(m0 + 64 + r) * HD + seg * 4];
                asm volatile("cp.async.ca.shared.global [%0], [%1], 16;" :: "r"(dst), "l"(src));
            }
            asm volatile("cp.async.commit_group;");
        }

        const float* Kb = buf[it & 1];

        // mask words for this 64-col span
        const unsigned m00 = __ldg(&mrow_lo[it * 2]);
        const unsigned m01 = __ldg(&mrow_lo[it * 2 + 1]);
        const unsigned m10 = __ldg(&mrow_hi[it * 2]);
        const unsigned m11 = __ldg(&mrow_hi[it * 2 + 1]);

        // ---- S = Q K^T ----
        float Sa[8][4];
        #pragma unroll
        for (int f = 0; f < 8; f++)
            #pragma unroll
            for (int e = 0; e < 4; e++) Sa[f][e] = 0.f;

        #pragma unroll
        for (int f = 0; f < 8; f++) {
            #pragma unroll
            for (int kc = 0; kc < 8; kc++) {
                unsigned b0 = __float_as_uint(Kb[(8 * f + g) * KSTR + 8 * kc + q]);
                unsigned b1 = __float_as_uint(Kb[(8 * f + g) * KSTR + 8 * kc + q + 4]);
                mma_tf32(Sa[f], Qa[kc][0], Qa[kc][1], Qa[kc][2], Qa[kc][3], b0, b1);
            }
        }

        // ---- mask + exp (in registers) + rowsum + stream E to gmem ----
        #pragma unroll
        for (int f = 0; f < 8; f++) {
            const unsigned wlo = (f < 4) ? m00 : m01;
            const unsigned whi = (f < 4) ? m10 : m11;
            const int sh = (8 * f + 2 * q) & 31;
            float e0 = ((wlo >> sh) & 1u)       ? f2tf32(__expf(Sa[f][0] * SCALE)) : 0.f;
            float e1 = ((wlo >> (sh + 1)) & 1u) ? f2tf32(__expf(Sa[f][1] * SCALE)) : 0.f;
            float e2 = ((whi >> sh) & 1u)       ? f2tf32(__expf(Sa[f][2] * SCALE)) : 0.f;
            float e3 = ((whi >> (sh + 1)) & 1u) ? f2tf32(__expf(Sa[f][3] * SCALE)) : 0.f;
            rs_lo += e0 + e1;
            rs_hi += e2 + e3;
            Sa[f][0] = e0; Sa[f][1] = e1; Sa[f][2] = e2; Sa[f][3] = e3;
            __stcs((float2*)&Srow_lo[m0 + 8 * f + 2 * q], make_float2(e0, e1));
            __stcs((float2*)&Srow_hi[m0 + 8 * f + 2 * q], make_float2(e2, e3));
        }

        // ---- O += E V  (A fragments from Sa via intra-quad shuffles) ----
        const int src1 = (lane & ~3) | (q >> 1);
        const int src2 = src1 + 2;
        const bool odd = q & 1;
        #pragma unroll
        for (int kc = 0; kc < 8; kc++) {
            float c0 = Sa[kc][0], c1 = Sa[kc][1], c2 = Sa[kc][2], c3 = Sa[kc][3];
            float v00 = __shfl_sync(0xffffffffu, c0, src1);
            float v01 = __shfl_sync(0xffffffffu, c1, src1);
            float v02 = __shfl_sync(0xffffffffu, c2, src1);
            float v03 = __shfl_sync(0xffffffffu, c3, src1);
            float v10 = __shfl_sync(0xffffffffu, c0, src2);
            float v11 = __shfl_sync(0xffffffffu, c1, src2);
            float v12 = __shfl_sync(0xffffffffu, c2, src2);
            float v13 = __shfl_sync(0xffffffffu, c3, src2);
            unsigned a0 = __float_as_uint(odd ? v01 : v00);
            unsigned a1 = __float_as_uint(odd ? v03 : v02);
            unsigned a2 = __float_as_uint(odd ? v11 : v10);
            unsigned a3 = __float_as_uint(odd ? v13 : v12);
            #pragma unroll
            for (int df = 0; df < 8; df++) {
                unsigned b0 = __float_as_uint(Kb[(8 * kc + q) * KSTR + 8 * df + g]);
                unsigned b1 = __float_as_uint(Kb[(8 * kc + q + 4) * KSTR + 8 * df + g]);
                mma_tf32(Oa[df], a0, a1, a2, a3, b0, b1);
            }
        }
    }

    // ---- epilogue: rowsum reduce, normalize, write O + rowsum ----
    rs_lo += __shfl_xor_sync(0xffffffffu, rs_lo, 1);
    rs_lo += __shfl_xor_sync(0xffffffffu, rs_lo, 2);
    rs_hi += __shfl_xor_sync(0xffffffffu, rs_hi, 1);
    rs_hi += __shfl_xor_sync(0xffffffffu, rs_hi, 2);
    if (q == 0) {
        g_rowsum[(size_t)bh * NN + r_lo] = rs_lo;
        g_rowsum[(size_t)bh * NN + r_hi] = rs_hi;
    }
    const float inv_lo = 1.f / rs_lo;
    const float inv_hi = 1.f / rs_hi;
    float* O_lo = &g_O[((size_t)b * NN + r_lo) * HD + hh * DD];
    float* O_hi = &g_O[((size_t)b * NN + r_hi) * HD + hh * DD];
    #pragma unroll
    for (int df = 0; df < 8; df++) {
        *(float2*)&O_lo[8 * df + 2 * q] = make_float2(Oa[df][0] * inv_lo, Oa[df][1] * inv_lo);
        *(float2*)&O_hi[8 * df + 2 * q] = make_float2(Oa[df][2] * inv_hi, Oa[df][3] * inv_hi);
    }
}

// ---------------------------------------------------------------------------
// K3: mean over heads of p = e / rowsum  -> out_mean
// ---------------------------------------------------------------------------
__global__ void k_mean(float* __restrict__ out_mean) {
    __shared__ float inv[HH];
    const int row = blockIdx.x;
    const int b = row >> 11;
    const int n = row & (NN - 1);
    const int t = threadIdx.x;

    if (t < HH) inv[t] = 0.125f / g_rowsum[(size_t)(b * HH + t) * NN + n];
    __syncthreads();

    float* mrow = out_mean + (size_t)row * NN;
    #pragma unroll
    for (int c4 = t; c4 < NN / 4; c4 += 256) {
        float4 acc = make_float4(0.f, 0.f, 0.f, 0.f);
        #pragma unroll
        for (int h = 0; h < HH; h++) {
            const float4 e4 = __ldcs((const float4*)&g_S[((size_t)(b * HH + h) * NN + n) * NN + c4 * 4]);
            float iv = inv[h];
            acc.x += e4.x * iv; acc.y += e4.y * iv;
            acc.z += e4.z * iv; acc.w += e4.w * iv;
        }
        *(float4*)&mrow[c4 * 4] = acc;
    }
}

// ---------------------------------------------------------------------------
// K5: LayerNorm -> out
// ---------------------------------------------------------------------------
__global__ void k_ln(const float* __restrict__ gamma, const float* __restrict__ beta,
                     float* __restrict__ out) {
    __shared__ float red[128];
    __shared__ float red2[128];

    const int row = blockIdx.x;
    const int t = threadIdx.x;
    const float* v = g_O + (size_t)row * HD;

    float s = 0.f, s2 = 0.f;
    float vals[4];
    #pragma unroll
    for (int i = 0; i < 4; i++) {
        vals[i] = v[t + i * 128];
        s += vals[i];
        s2 += vals[i] * vals[i];
    }
    red[t] = s; red2[t] = s2;
    __syncthreads();
    for (int st = 64; st > 0; st >>= 1) {
        if (t < st) { red[t] += red[t + st]; red2[t] += red2[t + st]; }
        __syncthreads();
    }
    const float mu = red[0] * (1.f / HD);
    const float var = red2[0] * (1.f / HD) - mu * mu;
    const float rstd = rsqrtf(var + EPS);

    float* orow = out + (size_t)row * HD;
    #pragma unroll
    for (int i = 0; i < 4; i++) {
        int c = t + i * 128;
        orow[c] = (vals[i] - mu) * rstd * gamma[c] + beta[c];
    }
}

// ---------------------------------------------------------------------------
extern "C" void kernel_launch(void* const* d_in, const int* in_sizes, int n_in,
                              void* d_out, int out_size) {
    const float* x     = (const float*)d_in[0];
    const int*   adj   = (const int*)d_in[1];
    const float* W_w   = (const float*)d_in[2];
    const float* W_b   = (const float*)d_in[3];
    const float* gamma = (const float*)d_in[4];
    const float* beta  = (const float*)d_in[5];
    float* out = (float*)d_out;
    float* out_mean = out + (size_t)BB * NN * HD;

    k_pack<<<BB * NN, 256>>>(adj);
    k_proj<<<dim3(HD / 64, (BB * NN) / 64), 128>>>(x, W_w, W_b);
    k_fused<<<dim3(NN / 256, BB * HH), 512>>>();
    k_mean<<<BB * NN, 256>>>(out_mean);
    k_ln<<<BB * NN, 128>>>(gamma, beta, out);
}